// round 12
// baseline (speedup 1.0000x reference)
#include <cuda_runtime.h>
#include <cuda_fp16.h>
#include <cstdint>
#include <cstddef>

// ============================================================================
// Problem constants. Harness dtypes: x/SCB/bias = float32 (fp16 values upcast
// losslessly), CB = int32, output = float32.
// ============================================================================
static constexpr int D_IN   = 4096;
static constexpr int D_OUT  = 11008;
static constexpr int M_TOT  = 8192;                 // 4 * 2048
static constexpr int BM     = 128;
static constexpr int BN     = 128;
static constexpr int BK     = 64;                   // halves per stage (128 B rows)
static constexpr int KITERS = D_IN / BK;            // 64
static constexpr int STAGES = 3;
static constexpr int TILES_M = M_TOT / BM;          // 64
static constexpr int TILES_N = D_OUT / BN;          // 86
static constexpr int A_BYTES = BM * BK * 2;         // 16 KB
static constexpr int STAGE_BYTES = (BM + BN) * BK * 2;  // 32 KB
static constexpr int SMEM_BYTES  = STAGES * STAGE_BYTES + 1024; // 97 KB

// Device-global scratch (allocation-free): fp16 copies of x and dequantized W
__device__ __align__(16) __half g_X[(size_t)M_TOT * D_IN];   // 64 MB
__device__ __align__(16) __half g_W[(size_t)D_OUT * D_IN];   // 90 MB

// ============================================================================
// Helpers
// ============================================================================
__device__ __forceinline__ uint32_t smem_u32(const void* p) {
    uint32_t a;
    asm("{ .reg .u64 t; cvta.to.shared.u64 t, %1; cvt.u32.u64 %0, t; }"
        : "=r"(a) : "l"(p));
    return a;
}

__device__ __forceinline__ void cp_async16(uint32_t dst, const void* src) {
    asm volatile("cp.async.cg.shared.global [%0], [%1], 16;"
                 :: "r"(dst), "l"(src) : "memory");
}
#define CP_COMMIT() asm volatile("cp.async.commit_group;" ::: "memory")
#define CP_WAIT1()  asm volatile("cp.async.wait_group 1;" ::: "memory")

// Named split barriers. CTA = 128 threads; each thread ARRIVEs once and SYNCs
// once per phase -> release count 256.
#define BAR_A_SYNC()   asm volatile("bar.sync 1, 256;" ::: "memory")
#define BAR_A_ARRIVE() asm volatile("bar.arrive 1, 256;" ::: "memory")
#define BAR_V_SYNC()   asm volatile("bar.sync 2, 256;" ::: "memory")
#define BAR_V_ARRIVE() asm volatile("bar.arrive 2, 256;" ::: "memory")

// ============================================================================
// Kernel 1 (merged prep): x fp32->fp16 AND dequant CB int32 -> W fp16.
// Dequant matches reference fp16 chain: s = fp16(SCB)/fp16(127); W = fp16(CB)*s.
// ============================================================================
static constexpr size_t NX_VEC = (size_t)M_TOT * D_IN / 8;     // 4,194,304
static constexpr size_t NW_VEC = (size_t)D_OUT * D_IN / 8;     // 5,636,096
static constexpr int PREP_BLOCKS = (int)((NX_VEC + NW_VEC) / 256);  // 38400

__global__ __launch_bounds__(256) void prep_kernel(const float* __restrict__ xf,
                                                   const int* __restrict__ CB,
                                                   const float* __restrict__ SCB) {
    size_t i = (size_t)blockIdx.x * 256 + threadIdx.x;
    if (i < NX_VEC) {
        const float4* p = (const float4*)xf + i * 2;
        float4 a = p[0], b = p[1];
        union { uint4 v; __half2 h[4]; } u;
        u.h[0] = __floats2half2_rn(a.x, a.y);
        u.h[1] = __floats2half2_rn(a.z, a.w);
        u.h[2] = __floats2half2_rn(b.x, b.y);
        u.h[3] = __floats2half2_rn(b.z, b.w);
        ((uint4*)g_X)[i] = u.v;
    } else {
        size_t j = i - NX_VEC;
        int n = (int)(j >> 9);                           // (j*8)/4096
        __half s = __hdiv(__float2half_rn(SCB[n]), __float2half(127.0f));
        const int4* p = (const int4*)CB + j * 2;
        int4 a = p[0], b = p[1];
        union { uint4 v; __half2 h[4]; } u;
        u.h[0] = __halves2half2(__hmul(__int2half_rn(a.x), s), __hmul(__int2half_rn(a.y), s));
        u.h[1] = __halves2half2(__hmul(__int2half_rn(a.z), s), __hmul(__int2half_rn(a.w), s));
        u.h[2] = __halves2half2(__hmul(__int2half_rn(b.x), s), __hmul(__int2half_rn(b.y), s));
        u.h[3] = __halves2half2(__hmul(__int2half_rn(b.z), s), __hmul(__int2half_rn(b.w), s));
        ((uint4*)g_W)[j] = u.v;
    }
}

// ============================================================================
// Kernel 2: mma.sync fp16 GEMM, fp16 ACCUMULATORS over K=128 windows with
// fp32 spill (interleaved into seg0's MMA stream). CTA 128x128x64, 4 warps
// (2x2), warp tile 64x64, 3-stage cp.async pipeline, 2 CTAs/SM, split named
// barriers, interleaved gmem prefetch at seg2. Single-buffered fragments
// (register budget goes to the dual accumulators).
//
// SW128 swizzle: sw(row, cb) = row*128 + (cb ^ ((row&7)<<4)); per-ks address
// trick: kb ∈ {0,32,64,96} -> addr(ks) = (stage_base + tile_const) ^ kb.
// ============================================================================
__device__ __forceinline__ void ld_frags(uint32_t sa, uint32_t kb,
                                         const uint32_t ta[4], const uint32_t tb[4],
                                         uint32_t RA[4][4], uint32_t RB[4][4]) {
#pragma unroll
    for (int mt = 0; mt < 4; ++mt) {
        uint32_t addr = (sa + ta[mt]) ^ kb;
        asm volatile("ldmatrix.sync.aligned.m8n8.x4.shared.b16 {%0,%1,%2,%3}, [%4];"
            : "=r"(RA[mt][0]), "=r"(RA[mt][1]), "=r"(RA[mt][2]), "=r"(RA[mt][3])
            : "r"(addr));
    }
#pragma unroll
    for (int p = 0; p < 4; ++p) {
        uint32_t addr = (sa + tb[p]) ^ kb;
        asm volatile("ldmatrix.sync.aligned.m8n8.x4.shared.b16 {%0,%1,%2,%3}, [%4];"
            : "=r"(RB[p][0]), "=r"(RB[p][1]), "=r"(RB[p][2]), "=r"(RB[p][3])
            : "r"(addr));
    }
}

// fp16-accumulate HMMA: D(f16x2 pair) = A*B + D
#define MMA16_ONE(dp, RAf, b0, b1)                                          \
    asm volatile(                                                           \
        "mma.sync.aligned.m16n8k16.row.col.f16.f16.f16.f16 "                \
        "{%0,%1}, {%2,%3,%4,%5}, {%6,%7}, {%0,%1};"                         \
        : "+r"((dp)[0]), "+r"((dp)[1])                                      \
        : "r"((RAf)[0]), "r"((RAf)[1]), "r"((RAf)[2]), "r"((RAf)[3]),       \
          "r"(b0), "r"(b1))

__device__ __forceinline__ void spill_one(float* a32, uint32_t* a16) {
    float2 lo = __half22float2(*reinterpret_cast<__half2*>(&a16[0]));
    float2 hi = __half22float2(*reinterpret_cast<__half2*>(&a16[1]));
    a32[0] += lo.x; a32[1] += lo.y; a32[2] += hi.x; a32[3] += hi.y;
    a16[0] = 0u; a16[1] = 0u;
}

__device__ __forceinline__ void mma_all16(uint32_t acc16[4][8][2],
                                          const uint32_t RA[4][4],
                                          const uint32_t RB[4][4]) {
#pragma unroll
    for (int mt = 0; mt < 4; ++mt)
#pragma unroll
        for (int nt = 0; nt < 8; ++nt)
            MMA16_ONE(acc16[mt][nt], RA[mt],
                      RB[nt >> 1][(nt & 1) * 2], RB[nt >> 1][(nt & 1) * 2 + 1]);
}

// seg0 with spill: spill acc j to fp32 right before acc j's first MMA of the
// new window, so the tensor pipe keeps a steady MMA stream during spills.
__device__ __forceinline__ void mma_seg0_spill(float acc32[4][8][4],
                                               uint32_t acc16[4][8][2],
                                               const uint32_t RA[4][4],
                                               const uint32_t RB[4][4]) {
#pragma unroll
    for (int i = 0; i < 32; ++i) {
        int mt = i >> 3, nt = i & 7;
        spill_one(acc32[mt][nt], acc16[mt][nt]);
        MMA16_ONE(acc16[mt][nt], RA[mt],
                  RB[nt >> 1][(nt & 1) * 2], RB[nt >> 1][(nt & 1) * 2 + 1]);
    }
}

// seg2 variant: 32 MMAs with 16 cp.async interleaved (one per 2 MMAs).
__device__ __forceinline__ void mma_all_ld16(uint32_t acc16[4][8][2],
                                             const uint32_t RA[4][4],
                                             const uint32_t RB[4][4],
                                             bool doload,
                                             uint32_t smA, uint32_t smB,
                                             const __half* pA, const __half* pB) {
#pragma unroll
    for (int i = 0; i < 32; ++i) {
        int mt = i >> 3, nt = i & 7;
        MMA16_ONE(acc16[mt][nt], RA[mt],
                  RB[nt >> 1][(nt & 1) * 2], RB[nt >> 1][(nt & 1) * 2 + 1]);
        if (!(i & 1) && doload) {
            int j = i >> 1;                         // 0..15
            if (j < 8) cp_async16(smA + (uint32_t)j * 2048, pA + (size_t)j * 16 * D_IN);
            else       cp_async16(smB + (uint32_t)(j - 8) * 2048,
                                  pB + (size_t)(j - 8) * 16 * D_IN);
        }
    }
}

__global__ __launch_bounds__(128, 2)
void gemm_kernel(const float* __restrict__ biasf,
                 float* __restrict__ out) {
    extern __shared__ char smem[];
    uint32_t sbA = (smem_u32(smem) + 1023u) & ~1023u;   // 1K-aligned stage base
    int tid  = threadIdx.x;
    int lane = tid & 31;
    int wid  = tid >> 5;         // 0..3
    int warp_m = wid >> 1;       // 0..1 (64 rows each)
    int warp_n = wid & 1;        // 0..1 (64 cols each)

    // Grouped rasterization: 8 m-tiles per supergroup, n fastest (B stays in L2)
    const int per = 8 * TILES_N;
    int g  = blockIdx.x / per;
    int r0 = blockIdx.x % per;
    int mi = g * 8 + (r0 & 7);
    int ni = r0 >> 3;
    int m0 = mi * BM;
    int n0 = ni * BN;

    // Per-thread gmem/smem constants for stage loading
    int lr = tid >> 3;           // 0..15
    int lc = tid & 7;            // 16B chunk
    uint32_t cbx = (uint32_t)(lc * 16) ^ (uint32_t)((lr & 7) << 4);
    const __half* pAg = g_X + (size_t)(m0 + lr) * D_IN + lc * 8;
    const __half* pBg = g_W + (size_t)(n0 + lr) * D_IN + lc * 8;
    uint32_t smO = (uint32_t)lr * 128 + cbx;   // smem offset within stage (A part)

    // Tile constants: toff = row*128 + (colbase ^ ((row&7)<<4))
    uint32_t ta[4], tb[4];
    {
        uint32_t acb = (uint32_t)((lane >> 4) * 16);
        uint32_t bcb = (uint32_t)(((lane >> 3) & 1) * 16);
#pragma unroll
        for (int mt = 0; mt < 4; ++mt) {
            int row = warp_m * 64 + mt * 16 + ((lane >> 3) & 1) * 8 + (lane & 7);
            ta[mt] = (uint32_t)row * 128 + (acb ^ (uint32_t)((row & 7) << 4));
        }
#pragma unroll
        for (int p = 0; p < 4; ++p) {
            int row = warp_n * 64 + p * 16 + ((lane >> 4) * 8) + (lane & 7);
            tb[p] = (uint32_t)A_BYTES + (uint32_t)row * 128 +
                    (bcb ^ (uint32_t)((row & 7) << 4));
        }
    }

    float acc32[4][8][4];
    uint32_t acc16[4][8][2];
#pragma unroll
    for (int i = 0; i < 4; ++i)
#pragma unroll
        for (int j = 0; j < 8; ++j) {
#pragma unroll
            for (int q = 0; q < 4; ++q) acc32[i][j][q] = 0.0f;
            acc16[i][j][0] = 0u; acc16[i][j][1] = 0u;
        }

    uint32_t RA[4][4], RB[4][4];

    // Prologue: fill stages 0,1; wait stage 0 (stage 1 stays in flight)
#pragma unroll
    for (int s = 0; s < 2; ++s) {
        uint32_t base = sbA + (uint32_t)s * STAGE_BYTES;
#pragma unroll
        for (int j = 0; j < 8; ++j) {
            cp_async16(base + smO + (uint32_t)j * 2048,
                       pAg + (size_t)j * 16 * D_IN + s * BK);
            cp_async16(base + A_BYTES + smO + (uint32_t)j * 2048,
                       pBg + (size_t)j * 16 * D_IN + s * BK);
        }
        CP_COMMIT();
    }
    CP_WAIT1();
    __syncthreads();
    BAR_A_ARRIVE();                                    // prime anti-dep phase 0

#pragma unroll 1
    for (int k = 0; k < KITERS; ++k) {
        uint32_t sa = sbA + (uint32_t)(k % STAGES) * STAGE_BYTES;

        // seg0: stage-k visibility, frags kb=0, MMAs (+ window spill on even k)
        if (k > 0) BAR_V_SYNC();
        ld_frags(sa, 0u, ta, tb, RA, RB);
        if (k >= 2 && !(k & 1)) mma_seg0_spill(acc32, acc16, RA, RB);
        else                    mma_all16(acc16, RA, RB);

        // seg1
        ld_frags(sa, 32u, ta, tb, RA, RB);
        mma_all16(acc16, RA, RB);

        // seg2: anti-dep barrier, then MMAs with interleaved stage-(k+2) loads
        ld_frags(sa, 64u, ta, tb, RA, RB);
        BAR_A_SYNC();              // all warps past last read of recycled stage
        {
            bool doload = (k + 2 < KITERS);
            uint32_t b2 = sbA + (uint32_t)((k + 2) % STAGES) * STAGE_BYTES;
            int k2 = (k + 2) * BK;
            mma_all_ld16(acc16, RA, RB, doload,
                         b2 + smO, b2 + A_BYTES + smO, pAg + k2, pBg + k2);
        }
        CP_COMMIT();               // unconditional: uniform group accounting
        CP_WAIT1();                // (k+1)-stage group has landed for this warp
        BAR_V_ARRIVE();            // publish visibility of stage k+1

        // seg3: last read (kb=96) of current stage, then release it
        ld_frags(sa, 96u, ta, tb, RA, RB);
        BAR_A_ARRIVE();            // done reading stage k (recycled at k+1 seg2)
        mma_all16(acc16, RA, RB);
    }

    // Final window spill (iters 62,63)
#pragma unroll
    for (int mt = 0; mt < 4; ++mt)
#pragma unroll
        for (int nt = 0; nt < 8; ++nt)
            spill_one(acc32[mt][nt], acc16[mt][nt]);

    // Epilogue: fp16(acc_f32) + fp16(bias), then upcast to fp32 output
    int t2 = (lane & 3) * 2;
    int gg = lane >> 2;
#pragma unroll
    for (int nt = 0; nt < 8; ++nt) {
        int col = n0 + warp_n * 64 + nt * 8 + t2;
        float2 bf = *(const float2*)(biasf + col);
        __half blo = __float2half_rn(bf.x);
        __half bhi = __float2half_rn(bf.y);
#pragma unroll
        for (int mt = 0; mt < 4; ++mt) {
            int row0 = m0 + warp_m * 64 + mt * 16 + gg;
            float2 v0 = make_float2(
                __half2float(__hadd(__float2half_rn(acc32[mt][nt][0]), blo)),
                __half2float(__hadd(__float2half_rn(acc32[mt][nt][1]), bhi)));
            *(float2*)(out + (size_t)row0 * D_OUT + col) = v0;
            float2 v1 = make_float2(
                __half2float(__hadd(__float2half_rn(acc32[mt][nt][2]), blo)),
                __half2float(__hadd(__float2half_rn(acc32[mt][nt][3]), bhi)));
            *(float2*)(out + (size_t)(row0 + 8) * D_OUT + col) = v1;
        }
    }
}

// ============================================================================
// Launch
// ============================================================================
extern "C" void kernel_launch(void* const* d_in, const int* in_sizes, int n_in,
                              void* d_out, int out_size) {
    const float* x    = (const float*)d_in[0];
    const int*   CB   = (const int*)d_in[1];
    const float* SCB  = (const float*)d_in[2];
    const float* bias = (const float*)d_in[3];
    float* out = (float*)d_out;

    // 1) Merged prep: x->fp16 and W dequant
    prep_kernel<<<PREP_BLOCKS, 256>>>(x, CB, SCB);

    // 2) Tensor-core GEMM (legacy mma.sync — tcgen05 blocked by the harness's
    //    compute_103 virtual-arch compile), 2 CTAs/SM, 64x64 warp tiles,
    //    fp16 window accumulation + fp32 spill, split barriers, interleaved
    //    prefetch.
    cudaFuncSetAttribute(gemm_kernel, cudaFuncAttributeMaxDynamicSharedMemorySize,
                         SMEM_BYTES);
    gemm_kernel<<<TILES_M * TILES_N, 128, SMEM_BYTES>>>(bias, out);
}

// round 13
// speedup vs baseline: 1.2804x; 1.2804x over previous
#include <cuda_runtime.h>
#include <cuda_fp16.h>
#include <cstdint>
#include <cstddef>

// ============================================================================
// Problem constants. Harness dtypes: x/SCB/bias = float32 (fp16 values upcast
// losslessly), CB = int32, output = float32.
// ============================================================================
static constexpr int D_IN   = 4096;
static constexpr int D_OUT  = 11008;
static constexpr int M_TOT  = 8192;                 // 4 * 2048
static constexpr int BM     = 128;
static constexpr int BN     = 128;
static constexpr int BK     = 64;                   // halves per stage (128 B rows)
static constexpr int KITERS = D_IN / BK;            // 64
static constexpr int STAGES = 3;
static constexpr int TILES_M = M_TOT / BM;          // 64
static constexpr int TILES_N = D_OUT / BN;          // 86
static constexpr int A_BYTES = BM * BK * 2;         // 16 KB
static constexpr int STAGE_BYTES = (BM + BN) * BK * 2;  // 32 KB
static constexpr int SMEM_BYTES  = STAGES * STAGE_BYTES + 1024; // 97 KB

// Device-global scratch (allocation-free): fp16 copies of x and dequantized W
__device__ __align__(16) __half g_X[(size_t)M_TOT * D_IN];   // 64 MB
__device__ __align__(16) __half g_W[(size_t)D_OUT * D_IN];   // 90 MB

// ============================================================================
// Helpers
// ============================================================================
__device__ __forceinline__ uint32_t smem_u32(const void* p) {
    uint32_t a;
    asm("{ .reg .u64 t; cvta.to.shared.u64 t, %1; cvt.u32.u64 %0, t; }"
        : "=r"(a) : "l"(p));
    return a;
}

__device__ __forceinline__ void cp_async16(uint32_t dst, const void* src) {
    asm volatile("cp.async.cg.shared.global [%0], [%1], 16;"
                 :: "r"(dst), "l"(src) : "memory");
}
#define CP_COMMIT() asm volatile("cp.async.commit_group;" ::: "memory")
#define CP_WAIT1()  asm volatile("cp.async.wait_group 1;" ::: "memory")

// Named split barriers. CTA = 128 threads; each thread ARRIVEs once and SYNCs
// once per phase -> release count 256.
#define BAR_A_SYNC()   asm volatile("bar.sync 1, 256;" ::: "memory")
#define BAR_A_ARRIVE() asm volatile("bar.arrive 1, 256;" ::: "memory")
#define BAR_V_SYNC()   asm volatile("bar.sync 2, 256;" ::: "memory")
#define BAR_V_ARRIVE() asm volatile("bar.arrive 2, 256;" ::: "memory")

// ============================================================================
// Kernel 1 (merged prep): x fp32->fp16 AND dequant CB int32 -> W fp16.
// Dequant matches reference fp16 chain: s = fp16(SCB)/fp16(127); W = fp16(CB)*s.
// ============================================================================
static constexpr size_t NX_VEC = (size_t)M_TOT * D_IN / 8;     // 4,194,304
static constexpr size_t NW_VEC = (size_t)D_OUT * D_IN / 8;     // 5,636,096
static constexpr int PREP_BLOCKS = (int)((NX_VEC + NW_VEC) / 256);  // 38400

__global__ __launch_bounds__(256) void prep_kernel(const float* __restrict__ xf,
                                                   const int* __restrict__ CB,
                                                   const float* __restrict__ SCB) {
    size_t i = (size_t)blockIdx.x * 256 + threadIdx.x;
    if (i < NX_VEC) {
        const float4* p = (const float4*)xf + i * 2;
        float4 a = p[0], b = p[1];
        union { uint4 v; __half2 h[4]; } u;
        u.h[0] = __floats2half2_rn(a.x, a.y);
        u.h[1] = __floats2half2_rn(a.z, a.w);
        u.h[2] = __floats2half2_rn(b.x, b.y);
        u.h[3] = __floats2half2_rn(b.z, b.w);
        ((uint4*)g_X)[i] = u.v;
    } else {
        size_t j = i - NX_VEC;
        int n = (int)(j >> 9);                           // (j*8)/4096
        __half s = __hdiv(__float2half_rn(SCB[n]), __float2half(127.0f));
        const int4* p = (const int4*)CB + j * 2;
        int4 a = p[0], b = p[1];
        union { uint4 v; __half2 h[4]; } u;
        u.h[0] = __halves2half2(__hmul(__int2half_rn(a.x), s), __hmul(__int2half_rn(a.y), s));
        u.h[1] = __halves2half2(__hmul(__int2half_rn(a.z), s), __hmul(__int2half_rn(a.w), s));
        u.h[2] = __halves2half2(__hmul(__int2half_rn(b.x), s), __hmul(__int2half_rn(b.y), s));
        u.h[3] = __halves2half2(__hmul(__int2half_rn(b.z), s), __hmul(__int2half_rn(b.w), s));
        ((uint4*)g_W)[j] = u.v;
    }
}

// ============================================================================
// Kernel 2 (R11 core): mma.sync fp16 GEMM, fp32 accumulators. CTA 128x128x64,
// 4 warps (2x2), warp tile 64x64, 3-stage cp.async pipeline, 2 CTAs/SM,
// register-double-buffered fragments, split named barriers, 16-LDGSTS stage
// prefetch interleaved into seg2's MMA stream. NEW vs R11: rotating stage
// pointers (no per-iter modular indexing) and elided dead tail sync work.
//
// SW128 swizzle: sw(row, cb) = row*128 + (cb ^ ((row&7)<<4)); per-ks address
// trick: kb ∈ {0,32,64,96} -> addr(ks) = (stage_base + tile_const) ^ kb.
// ============================================================================
__device__ __forceinline__ void ld_frags(uint32_t sa, uint32_t kb,
                                         const uint32_t ta[4], const uint32_t tb[4],
                                         uint32_t RA[4][4], uint32_t RB[4][4]) {
#pragma unroll
    for (int mt = 0; mt < 4; ++mt) {
        uint32_t addr = (sa + ta[mt]) ^ kb;
        asm volatile("ldmatrix.sync.aligned.m8n8.x4.shared.b16 {%0,%1,%2,%3}, [%4];"
            : "=r"(RA[mt][0]), "=r"(RA[mt][1]), "=r"(RA[mt][2]), "=r"(RA[mt][3])
            : "r"(addr));
    }
#pragma unroll
    for (int p = 0; p < 4; ++p) {
        uint32_t addr = (sa + tb[p]) ^ kb;
        asm volatile("ldmatrix.sync.aligned.m8n8.x4.shared.b16 {%0,%1,%2,%3}, [%4];"
            : "=r"(RB[p][0]), "=r"(RB[p][1]), "=r"(RB[p][2]), "=r"(RB[p][3])
            : "r"(addr));
    }
}

#define MMA_ONE(accp, RAf, b0, b1)                                          \
    asm volatile(                                                           \
        "mma.sync.aligned.m16n8k16.row.col.f32.f16.f16.f32 "                \
        "{%0,%1,%2,%3}, {%4,%5,%6,%7}, {%8,%9}, {%0,%1,%2,%3};"             \
        : "+f"((accp)[0]), "+f"((accp)[1]), "+f"((accp)[2]), "+f"((accp)[3])\
        : "r"((RAf)[0]), "r"((RAf)[1]), "r"((RAf)[2]), "r"((RAf)[3]),       \
          "r"(b0), "r"(b1))

__device__ __forceinline__ void mma_all(float acc[4][8][4],
                                        const uint32_t RA[4][4],
                                        const uint32_t RB[4][4]) {
#pragma unroll
    for (int mt = 0; mt < 4; ++mt)
#pragma unroll
        for (int nt = 0; nt < 8; ++nt)
            MMA_ONE(acc[mt][nt], RA[mt],
                    RB[nt >> 1][(nt & 1) * 2], RB[nt >> 1][(nt & 1) * 2 + 1]);
}

// seg2 variant: 32 MMAs with 16 cp.async interleaved (one per 2 MMAs).
__device__ __forceinline__ void mma_all_ld(float acc[4][8][4],
                                           const uint32_t RA[4][4],
                                           const uint32_t RB[4][4],
                                           bool doload,
                                           uint32_t smA, uint32_t smB,
                                           const __half* pA, const __half* pB) {
#pragma unroll
    for (int i = 0; i < 32; ++i) {
        int mt = i >> 3, nt = i & 7;
        MMA_ONE(acc[mt][nt], RA[mt],
                RB[nt >> 1][(nt & 1) * 2], RB[nt >> 1][(nt & 1) * 2 + 1]);
        if (!(i & 1) && doload) {
            int j = i >> 1;                         // 0..15
            if (j < 8) cp_async16(smA + (uint32_t)j * 2048, pA + (size_t)j * 16 * D_IN);
            else       cp_async16(smB + (uint32_t)(j - 8) * 2048,
                                  pB + (size_t)(j - 8) * 16 * D_IN);
        }
    }
}

__global__ __launch_bounds__(128, 2)
void gemm_kernel(const float* __restrict__ biasf,
                 float* __restrict__ out) {
    extern __shared__ char smem[];
    uint32_t sbA = (smem_u32(smem) + 1023u) & ~1023u;   // 1K-aligned stage base
    int tid  = threadIdx.x;
    int lane = tid & 31;
    int wid  = tid >> 5;         // 0..3
    int warp_m = wid >> 1;       // 0..1 (64 rows each)
    int warp_n = wid & 1;        // 0..1 (64 cols each)

    // Grouped rasterization: 8 m-tiles per supergroup, n fastest (B stays in L2)
    const int per = 8 * TILES_N;
    int g  = blockIdx.x / per;
    int r0 = blockIdx.x % per;
    int mi = g * 8 + (r0 & 7);
    int ni = r0 >> 3;
    int m0 = mi * BM;
    int n0 = ni * BN;

    // Per-thread gmem/smem constants for stage loading
    int lr = tid >> 3;           // 0..15
    int lc = tid & 7;            // 16B chunk
    uint32_t cbx = (uint32_t)(lc * 16) ^ (uint32_t)((lr & 7) << 4);
    const __half* pAg = g_X + (size_t)(m0 + lr) * D_IN + lc * 8;
    const __half* pBg = g_W + (size_t)(n0 + lr) * D_IN + lc * 8;
    uint32_t smO = (uint32_t)lr * 128 + cbx;   // smem offset within stage (A part)

    // Tile constants: toff = row*128 + (colbase ^ ((row&7)<<4))
    uint32_t ta[4], tb[4];
    {
        uint32_t acb = (uint32_t)((lane >> 4) * 16);
        uint32_t bcb = (uint32_t)(((lane >> 3) & 1) * 16);
#pragma unroll
        for (int mt = 0; mt < 4; ++mt) {
            int row = warp_m * 64 + mt * 16 + ((lane >> 3) & 1) * 8 + (lane & 7);
            ta[mt] = (uint32_t)row * 128 + (acb ^ (uint32_t)((row & 7) << 4));
        }
#pragma unroll
        for (int p = 0; p < 4; ++p) {
            int row = warp_n * 64 + p * 16 + ((lane >> 4) * 8) + (lane & 7);
            tb[p] = (uint32_t)A_BYTES + (uint32_t)row * 128 +
                    (bcb ^ (uint32_t)((row & 7) << 4));
        }
    }

    float acc[4][8][4];
#pragma unroll
    for (int i = 0; i < 4; ++i)
#pragma unroll
        for (int j = 0; j < 8; ++j)
#pragma unroll
            for (int q = 0; q < 4; ++q) acc[i][j][q] = 0.0f;

    uint32_t RA[2][4][4], RB[2][4][4];

    // Rotating stage pointers: s0 = stage k, s1 = stage k+1, s2 = stage k+2
    uint32_t s0 = sbA, s1 = sbA + STAGE_BYTES, s2 = sbA + 2 * STAGE_BYTES;

    // Prologue: fill stages 0,1 (burst form is fine here — nothing to overlap)
#pragma unroll
    for (int s = 0; s < 2; ++s) {
        uint32_t base = sbA + (uint32_t)s * STAGE_BYTES;
#pragma unroll
        for (int j = 0; j < 8; ++j) {
            cp_async16(base + smO + (uint32_t)j * 2048,
                       pAg + (size_t)j * 16 * D_IN + s * BK);
            cp_async16(base + A_BYTES + smO + (uint32_t)j * 2048,
                       pBg + (size_t)j * 16 * D_IN + s * BK);
        }
        CP_COMMIT();
    }
    CP_WAIT1();
    __syncthreads();
    ld_frags(s0, 0, ta, tb, RA[0], RB[0]);
    BAR_A_ARRIVE();                                    // prime anti-dep phase 0

#pragma unroll 1
    for (int k = 0; k < KITERS; ++k) {
        const bool last = (k == KITERS - 1);

        // seg0: consume buf0, load frags(k, kb=32) into buf1
        ld_frags(s0, 32u, ta, tb, RA[1], RB[1]);
        mma_all(acc, RA[0], RB[0]);

        // seg1: consume buf1, load frags(k, kb=64) into buf0
        ld_frags(s0, 64u, ta, tb, RA[0], RB[0]);
        mma_all(acc, RA[1], RB[1]);

        // seg2: consume buf0; last read (kb=96) of the recycled stage into buf1;
        // then anti-dep barrier and the INTERLEAVED stage-(k+2) prefetch.
        ld_frags(s0, 96u, ta, tb, RA[1], RB[1]);
        if (!last) {
            BAR_A_SYNC();          // all warps done reading the recycled stage
            {
                bool doload = (k + 2 < KITERS);
                int k2 = (k + 2) * BK;
                mma_all_ld(acc, RA[0], RB[0], doload,
                           s2 + smO, s2 + A_BYTES + smO, pAg + k2, pBg + k2);
            }
            CP_COMMIT();           // unconditional: uniform group accounting
            CP_WAIT1();            // (k+1)-stage group has landed for this warp
            BAR_V_ARRIVE();        // publish visibility
            BAR_A_ARRIVE();        // done reading current stage (next recycle)

            // seg3: consume buf1; load frags(k+1, kb=0) from next stage
            BAR_V_SYNC();          // everyone's (k+1)-stage loads visible
            ld_frags(s1, 0, ta, tb, RA[0], RB[0]);
            mma_all(acc, RA[1], RB[1]);
        } else {
            // Tail: no prefetch, no sync partners downstream — just finish.
            mma_all(acc, RA[0], RB[0]);
            mma_all(acc, RA[1], RB[1]);
        }

        // rotate stage ring
        uint32_t tmp = s0; s0 = s1; s1 = s2; s2 = tmp;
    }

    // Epilogue: fp16(acc_f32) + fp16(bias), then upcast to fp32 output
    int t2 = (lane & 3) * 2;
    int gg = lane >> 2;
#pragma unroll
    for (int nt = 0; nt < 8; ++nt) {
        int col = n0 + warp_n * 64 + nt * 8 + t2;
        float2 bf = *(const float2*)(biasf + col);
        __half blo = __float2half_rn(bf.x);
        __half bhi = __float2half_rn(bf.y);
#pragma unroll
        for (int mt = 0; mt < 4; ++mt) {
            int row0 = m0 + warp_m * 64 + mt * 16 + gg;
            float2 v0 = make_float2(
                __half2float(__hadd(__float2half_rn(acc[mt][nt][0]), blo)),
                __half2float(__hadd(__float2half_rn(acc[mt][nt][1]), bhi)));
            *(float2*)(out + (size_t)row0 * D_OUT + col) = v0;
            float2 v1 = make_float2(
                __half2float(__hadd(__float2half_rn(acc[mt][nt][2]), blo)),
                __half2float(__hadd(__float2half_rn(acc[mt][nt][3]), bhi)));
            *(float2*)(out + (size_t)(row0 + 8) * D_OUT + col) = v1;
        }
    }
}

// ============================================================================
// Launch
// ============================================================================
extern "C" void kernel_launch(void* const* d_in, const int* in_sizes, int n_in,
                              void* d_out, int out_size) {
    const float* x    = (const float*)d_in[0];
    const int*   CB   = (const int*)d_in[1];
    const float* SCB  = (const float*)d_in[2];
    const float* bias = (const float*)d_in[3];
    float* out = (float*)d_out;

    // 1) Merged prep: x->fp16 and W dequant
    prep_kernel<<<PREP_BLOCKS, 256>>>(x, CB, SCB);

    // 2) Tensor-core GEMM (legacy mma.sync — tcgen05 blocked by the harness's
    //    compute_103 virtual-arch compile; fp16-accum HMMA measured 1x rate,
    //    so fp32 accum is strictly better), 2 CTAs/SM, 64x64 warp tiles,
    //    fragment double-buffering, split barriers, interleaved prefetch.
    cudaFuncSetAttribute(gemm_kernel, cudaFuncAttributeMaxDynamicSharedMemorySize,
                         SMEM_BYTES);
    gemm_kernel<<<TILES_M * TILES_N, 128, SMEM_BYTES>>>(bias, out);
}

// round 14
// speedup vs baseline: 1.2868x; 1.0050x over previous
#include <cuda_runtime.h>
#include <cuda_fp16.h>
#include <cstdint>
#include <cstddef>

// ============================================================================
// Problem constants. Harness dtypes: x/SCB/bias = float32 (fp16 values upcast
// losslessly), CB = int32, output = float32.
// ============================================================================
static constexpr int D_IN   = 4096;
static constexpr int D_OUT  = 11008;
static constexpr int M_TOT  = 8192;                 // 4 * 2048
static constexpr int BM     = 128;
static constexpr int BN     = 128;
static constexpr int BK     = 64;                   // halves per stage (128 B rows)
static constexpr int KITERS = D_IN / BK;            // 64
static constexpr int STAGES = 3;
static constexpr int TILES_M = M_TOT / BM;          // 64
static constexpr int TILES_N = D_OUT / BN;          // 86
static constexpr int A_BYTES = BM * BK * 2;         // 16 KB
static constexpr int STAGE_BYTES = (BM + BN) * BK * 2;  // 32 KB
static constexpr int SMEM_BYTES  = STAGES * STAGE_BYTES + 1024; // 97 KB

// Device-global scratch (allocation-free): fp16 copies of x and dequantized W
__device__ __align__(16) __half g_X[(size_t)M_TOT * D_IN];   // 64 MB
__device__ __align__(16) __half g_W[(size_t)D_OUT * D_IN];   // 90 MB

// ============================================================================
// Helpers
// ============================================================================
__device__ __forceinline__ uint32_t smem_u32(const void* p) {
    uint32_t a;
    asm("{ .reg .u64 t; cvta.to.shared.u64 t, %1; cvt.u32.u64 %0, t; }"
        : "=r"(a) : "l"(p));
    return a;
}

__device__ __forceinline__ void cp_async16(uint32_t dst, const void* src) {
    asm volatile("cp.async.cg.shared.global [%0], [%1], 16;"
                 :: "r"(dst), "l"(src) : "memory");
}
#define CP_COMMIT() asm volatile("cp.async.commit_group;" ::: "memory")
#define CP_WAIT1()  asm volatile("cp.async.wait_group 1;" ::: "memory")

// ============================================================================
// Kernel 1 (merged prep): x fp32->fp16 AND dequant CB int32 -> W fp16.
// Dequant matches reference fp16 chain: s = fp16(SCB)/fp16(127); W = fp16(CB)*s.
// ============================================================================
static constexpr size_t NX_VEC = (size_t)M_TOT * D_IN / 8;     // 4,194,304
static constexpr size_t NW_VEC = (size_t)D_OUT * D_IN / 8;     // 5,636,096
static constexpr int PREP_BLOCKS = (int)((NX_VEC + NW_VEC) / 256);  // 38400

__global__ __launch_bounds__(256) void prep_kernel(const float* __restrict__ xf,
                                                   const int* __restrict__ CB,
                                                   const float* __restrict__ SCB) {
    size_t i = (size_t)blockIdx.x * 256 + threadIdx.x;
    if (i < NX_VEC) {
        const float4* p = (const float4*)xf + i * 2;
        float4 a = p[0], b = p[1];
        union { uint4 v; __half2 h[4]; } u;
        u.h[0] = __floats2half2_rn(a.x, a.y);
        u.h[1] = __floats2half2_rn(a.z, a.w);
        u.h[2] = __floats2half2_rn(b.x, b.y);
        u.h[3] = __floats2half2_rn(b.z, b.w);
        ((uint4*)g_X)[i] = u.v;
    } else {
        size_t j = i - NX_VEC;
        int n = (int)(j >> 9);                           // (j*8)/4096
        __half s = __hdiv(__float2half_rn(SCB[n]), __float2half(127.0f));
        const int4* p = (const int4*)CB + j * 2;
        int4 a = p[0], b = p[1];
        union { uint4 v; __half2 h[4]; } u;
        u.h[0] = __halves2half2(__hmul(__int2half_rn(a.x), s), __hmul(__int2half_rn(a.y), s));
        u.h[1] = __halves2half2(__hmul(__int2half_rn(a.z), s), __hmul(__int2half_rn(a.w), s));
        u.h[2] = __halves2half2(__hmul(__int2half_rn(b.x), s), __hmul(__int2half_rn(b.y), s));
        u.h[3] = __halves2half2(__hmul(__int2half_rn(b.z), s), __hmul(__int2half_rn(b.w), s));
        ((uint4*)g_W)[j] = u.v;
    }
}

// ============================================================================
// Kernel 2: mma.sync fp16 GEMM, fp32 accumulators. CTA 128x128x64, 4 warps
// (2x2), warp tile 64x64, 3-stage cp.async pipeline (rotating pointers),
// 2 CTAs/SM, register-double-buffered fragments, interleaved seg2 prefetch,
// and a SINGLE __syncthreads per k-iteration:
//   - placed after CP_WAIT1 (stage k+1 group retired) and before seg3's first
//     read of stage k+1 -> visibility.
//   - iter k's cp.asyncs overwrite stage k-1, whose last read (kb=96) is at
//     iter k-1 seg2-START, i.e. before iter k-1's barrier -> the PREVIOUS
//     iteration's barrier is the anti-dependence guard. Between consecutive
//     barriers no warp touches the recycled stage.
//
// SW128 swizzle: sw(row, cb) = row*128 + (cb ^ ((row&7)<<4)); per-ks address
// trick: kb ∈ {0,32,64,96} -> addr(ks) = (stage_base + tile_const) ^ kb.
// ============================================================================
__device__ __forceinline__ void ld_frags(uint32_t sa, uint32_t kb,
                                         const uint32_t ta[4], const uint32_t tb[4],
                                         uint32_t RA[4][4], uint32_t RB[4][4]) {
#pragma unroll
    for (int mt = 0; mt < 4; ++mt) {
        uint32_t addr = (sa + ta[mt]) ^ kb;
        asm volatile("ldmatrix.sync.aligned.m8n8.x4.shared.b16 {%0,%1,%2,%3}, [%4];"
            : "=r"(RA[mt][0]), "=r"(RA[mt][1]), "=r"(RA[mt][2]), "=r"(RA[mt][3])
            : "r"(addr));
    }
#pragma unroll
    for (int p = 0; p < 4; ++p) {
        uint32_t addr = (sa + tb[p]) ^ kb;
        asm volatile("ldmatrix.sync.aligned.m8n8.x4.shared.b16 {%0,%1,%2,%3}, [%4];"
            : "=r"(RB[p][0]), "=r"(RB[p][1]), "=r"(RB[p][2]), "=r"(RB[p][3])
            : "r"(addr));
    }
}

#define MMA_ONE(accp, RAf, b0, b1)                                          \
    asm volatile(                                                           \
        "mma.sync.aligned.m16n8k16.row.col.f32.f16.f16.f32 "                \
        "{%0,%1,%2,%3}, {%4,%5,%6,%7}, {%8,%9}, {%0,%1,%2,%3};"             \
        : "+f"((accp)[0]), "+f"((accp)[1]), "+f"((accp)[2]), "+f"((accp)[3])\
        : "r"((RAf)[0]), "r"((RAf)[1]), "r"((RAf)[2]), "r"((RAf)[3]),       \
          "r"(b0), "r"(b1))

__device__ __forceinline__ void mma_all(float acc[4][8][4],
                                        const uint32_t RA[4][4],
                                        const uint32_t RB[4][4]) {
#pragma unroll
    for (int mt = 0; mt < 4; ++mt)
#pragma unroll
        for (int nt = 0; nt < 8; ++nt)
            MMA_ONE(acc[mt][nt], RA[mt],
                    RB[nt >> 1][(nt & 1) * 2], RB[nt >> 1][(nt & 1) * 2 + 1]);
}

// seg2 variant: 32 MMAs with 16 cp.async interleaved (one per 2 MMAs).
__device__ __forceinline__ void mma_all_ld(float acc[4][8][4],
                                           const uint32_t RA[4][4],
                                           const uint32_t RB[4][4],
                                           bool doload,
                                           uint32_t smA, uint32_t smB,
                                           const __half* pA, const __half* pB) {
#pragma unroll
    for (int i = 0; i < 32; ++i) {
        int mt = i >> 3, nt = i & 7;
        MMA_ONE(acc[mt][nt], RA[mt],
                RB[nt >> 1][(nt & 1) * 2], RB[nt >> 1][(nt & 1) * 2 + 1]);
        if (!(i & 1) && doload) {
            int j = i >> 1;                         // 0..15
            if (j < 8) cp_async16(smA + (uint32_t)j * 2048, pA + (size_t)j * 16 * D_IN);
            else       cp_async16(smB + (uint32_t)(j - 8) * 2048,
                                  pB + (size_t)(j - 8) * 16 * D_IN);
        }
    }
}

__global__ __launch_bounds__(128, 2)
void gemm_kernel(const float* __restrict__ biasf,
                 float* __restrict__ out) {
    extern __shared__ char smem[];
    uint32_t sbA = (smem_u32(smem) + 1023u) & ~1023u;   // 1K-aligned stage base
    int tid  = threadIdx.x;
    int lane = tid & 31;
    int wid  = tid >> 5;         // 0..3
    int warp_m = wid >> 1;       // 0..1 (64 rows each)
    int warp_n = wid & 1;        // 0..1 (64 cols each)

    // Grouped rasterization: 8 m-tiles per supergroup, n fastest (B stays in L2)
    const int per = 8 * TILES_N;
    int g  = blockIdx.x / per;
    int r0 = blockIdx.x % per;
    int mi = g * 8 + (r0 & 7);
    int ni = r0 >> 3;
    int m0 = mi * BM;
    int n0 = ni * BN;

    // Per-thread gmem/smem constants for stage loading
    int lr = tid >> 3;           // 0..15
    int lc = tid & 7;            // 16B chunk
    uint32_t cbx = (uint32_t)(lc * 16) ^ (uint32_t)((lr & 7) << 4);
    const __half* pAg = g_X + (size_t)(m0 + lr) * D_IN + lc * 8;
    const __half* pBg = g_W + (size_t)(n0 + lr) * D_IN + lc * 8;
    uint32_t smO = (uint32_t)lr * 128 + cbx;   // smem offset within stage (A part)

    // Tile constants: toff = row*128 + (colbase ^ ((row&7)<<4))
    uint32_t ta[4], tb[4];
    {
        uint32_t acb = (uint32_t)((lane >> 4) * 16);
        uint32_t bcb = (uint32_t)(((lane >> 3) & 1) * 16);
#pragma unroll
        for (int mt = 0; mt < 4; ++mt) {
            int row = warp_m * 64 + mt * 16 + ((lane >> 3) & 1) * 8 + (lane & 7);
            ta[mt] = (uint32_t)row * 128 + (acb ^ (uint32_t)((row & 7) << 4));
        }
#pragma unroll
        for (int p = 0; p < 4; ++p) {
            int row = warp_n * 64 + p * 16 + ((lane >> 4) * 8) + (lane & 7);
            tb[p] = (uint32_t)A_BYTES + (uint32_t)row * 128 +
                    (bcb ^ (uint32_t)((row & 7) << 4));
        }
    }

    float acc[4][8][4];
#pragma unroll
    for (int i = 0; i < 4; ++i)
#pragma unroll
        for (int j = 0; j < 8; ++j)
#pragma unroll
            for (int q = 0; q < 4; ++q) acc[i][j][q] = 0.0f;

    uint32_t RA[2][4][4], RB[2][4][4];

    // Rotating stage pointers: s0 = stage k, s1 = stage k+1, s2 = stage k+2
    uint32_t s0 = sbA, s1 = sbA + STAGE_BYTES, s2 = sbA + 2 * STAGE_BYTES;

    // Prologue: fill stages 0,1; wait stage 0 (stage 1 stays in flight)
#pragma unroll
    for (int s = 0; s < 2; ++s) {
        uint32_t base = sbA + (uint32_t)s * STAGE_BYTES;
#pragma unroll
        for (int j = 0; j < 8; ++j) {
            cp_async16(base + smO + (uint32_t)j * 2048,
                       pAg + (size_t)j * 16 * D_IN + s * BK);
            cp_async16(base + A_BYTES + smO + (uint32_t)j * 2048,
                       pBg + (size_t)j * 16 * D_IN + s * BK);
        }
        CP_COMMIT();
    }
    CP_WAIT1();
    __syncthreads();
    ld_frags(s0, 0, ta, tb, RA[0], RB[0]);

#pragma unroll 1
    for (int k = 0; k < KITERS; ++k) {
        const bool last = (k == KITERS - 1);

        // seg0: consume buf0, load frags(k, kb=32) into buf1
        ld_frags(s0, 32u, ta, tb, RA[1], RB[1]);
        mma_all(acc, RA[0], RB[0]);

        // seg1: consume buf1, load frags(k, kb=64) into buf0
        ld_frags(s0, 64u, ta, tb, RA[0], RB[0]);
        mma_all(acc, RA[1], RB[1]);

        // seg2: LAST read (kb=96) of stage k into buf1, then consume buf0 with
        // the interleaved stage-(k+2) prefetch (anti-dep guard = PREVIOUS
        // iteration's barrier), then wait + the single barrier.
        ld_frags(s0, 96u, ta, tb, RA[1], RB[1]);
        if (!last) {
            bool doload = (k + 2 < KITERS);
            int k2 = (k + 2) * BK;
            mma_all_ld(acc, RA[0], RB[0], doload,
                       s2 + smO, s2 + A_BYTES + smO, pAg + k2, pBg + k2);
            CP_COMMIT();           // unconditional: uniform group accounting
            CP_WAIT1();            // retires stage-(k+1) group for this warp
            __syncthreads();       // single barrier: visibility of stage k+1
                                   // + anti-dep guard for NEXT iter's cp.asyncs

            // seg3: consume buf1; load frags(k+1, kb=0) from next stage
            ld_frags(s1, 0, ta, tb, RA[0], RB[0]);
            mma_all(acc, RA[1], RB[1]);
        } else {
            // Tail: no prefetch, no downstream consumers — just finish.
            mma_all(acc, RA[0], RB[0]);
            mma_all(acc, RA[1], RB[1]);
        }

        // rotate stage ring
        uint32_t tmp = s0; s0 = s1; s1 = s2; s2 = tmp;
    }

    // Epilogue: fp16(acc_f32) + fp16(bias), then upcast to fp32 output
    int t2 = (lane & 3) * 2;
    int gg = lane >> 2;
#pragma unroll
    for (int nt = 0; nt < 8; ++nt) {
        int col = n0 + warp_n * 64 + nt * 8 + t2;
        float2 bf = *(const float2*)(biasf + col);
        __half blo = __float2half_rn(bf.x);
        __half bhi = __float2half_rn(bf.y);
#pragma unroll
        for (int mt = 0; mt < 4; ++mt) {
            int row0 = m0 + warp_m * 64 + mt * 16 + gg;
            float2 v0 = make_float2(
                __half2float(__hadd(__float2half_rn(acc[mt][nt][0]), blo)),
                __half2float(__hadd(__float2half_rn(acc[mt][nt][1]), bhi)));
            *(float2*)(out + (size_t)row0 * D_OUT + col) = v0;
            float2 v1 = make_float2(
                __half2float(__hadd(__float2half_rn(acc[mt][nt][2]), blo)),
                __half2float(__hadd(__float2half_rn(acc[mt][nt][3]), bhi)));
            *(float2*)(out + (size_t)(row0 + 8) * D_OUT + col) = v1;
        }
    }
}

// ============================================================================
// Launch
// ============================================================================
extern "C" void kernel_launch(void* const* d_in, const int* in_sizes, int n_in,
                              void* d_out, int out_size) {
    const float* x    = (const float*)d_in[0];
    const int*   CB   = (const int*)d_in[1];
    const float* SCB  = (const float*)d_in[2];
    const float* bias = (const float*)d_in[3];
    float* out = (float*)d_out;

    // 1) Merged prep: x->fp16 and W dequant
    prep_kernel<<<PREP_BLOCKS, 256>>>(x, CB, SCB);

    // 2) Tensor-core GEMM (legacy mma.sync — tcgen05 blocked by the harness's
    //    compute_103 virtual-arch compile; fp16-accum HMMA measured 1x rate),
    //    2 CTAs/SM, 64x64 warp tiles, fragment double-buffering, interleaved
    //    prefetch, single barrier per k-iteration.
    cudaFuncSetAttribute(gemm_kernel, cudaFuncAttributeMaxDynamicSharedMemorySize,
                         SMEM_BYTES);
    gemm_kernel<<<TILES_M * TILES_N, 128, SMEM_BYTES>>>(bias, out);
}

// round 15
// speedup vs baseline: 1.2895x; 1.0021x over previous
#include <cuda_runtime.h>
#include <cuda_fp16.h>
#include <cstdint>
#include <cstddef>

// ============================================================================
// Problem constants. Harness dtypes: x/SCB/bias = float32 (fp16 values upcast
// losslessly), CB = int32, output = float32.
// ============================================================================
static constexpr int D_IN   = 4096;
static constexpr int D_OUT  = 11008;
static constexpr int M_TOT  = 8192;                 // 4 * 2048
static constexpr int BM     = 128;
static constexpr int BN     = 128;
static constexpr int BK     = 64;                   // halves per stage (128 B rows)
static constexpr int KITERS = D_IN / BK;            // 64
static constexpr int STAGES = 3;
static constexpr int TILES_M = M_TOT / BM;          // 64
static constexpr int TILES_N = D_OUT / BN;          // 86
static constexpr int A_BYTES = BM * BK * 2;         // 16 KB
static constexpr int STAGE_BYTES = (BM + BN) * BK * 2;  // 32 KB
static constexpr int SMEM_BYTES  = STAGES * STAGE_BYTES + 1024; // 97 KB

// Device-global scratch (allocation-free): fp16 copies of x and dequantized W
__device__ __align__(16) __half g_X[(size_t)M_TOT * D_IN];   // 64 MB
__device__ __align__(16) __half g_W[(size_t)D_OUT * D_IN];   // 90 MB

// ============================================================================
// Helpers
// ============================================================================
__device__ __forceinline__ uint32_t smem_u32(const void* p) {
    uint32_t a;
    asm("{ .reg .u64 t; cvta.to.shared.u64 t, %1; cvt.u32.u64 %0, t; }"
        : "=r"(a) : "l"(p));
    return a;
}

__device__ __forceinline__ void cp_async16(uint32_t dst, const void* src) {
    asm volatile("cp.async.cg.shared.global [%0], [%1], 16;"
                 :: "r"(dst), "l"(src) : "memory");
}
#define CP_COMMIT() asm volatile("cp.async.commit_group;" ::: "memory")
#define CP_WAIT1()  asm volatile("cp.async.wait_group 1;" ::: "memory")

// ============================================================================
// Kernel 1 (merged prep): x fp32->fp16 AND dequant CB int32 -> W fp16.
// Dequant matches reference fp16 chain: s = fp16(SCB)/fp16(127); W = fp16(CB)*s.
// ============================================================================
static constexpr size_t NX_VEC = (size_t)M_TOT * D_IN / 8;     // 4,194,304
static constexpr size_t NW_VEC = (size_t)D_OUT * D_IN / 8;     // 5,636,096
static constexpr int PREP_BLOCKS = (int)((NX_VEC + NW_VEC) / 256);  // 38400

__global__ __launch_bounds__(256) void prep_kernel(const float* __restrict__ xf,
                                                   const int* __restrict__ CB,
                                                   const float* __restrict__ SCB) {
    size_t i = (size_t)blockIdx.x * 256 + threadIdx.x;
    if (i < NX_VEC) {
        const float4* p = (const float4*)xf + i * 2;
        float4 a = p[0], b = p[1];
        union { uint4 v; __half2 h[4]; } u;
        u.h[0] = __floats2half2_rn(a.x, a.y);
        u.h[1] = __floats2half2_rn(a.z, a.w);
        u.h[2] = __floats2half2_rn(b.x, b.y);
        u.h[3] = __floats2half2_rn(b.z, b.w);
        ((uint4*)g_X)[i] = u.v;
    } else {
        size_t j = i - NX_VEC;
        int n = (int)(j >> 9);                           // (j*8)/4096
        __half s = __hdiv(__float2half_rn(SCB[n]), __float2half(127.0f));
        const int4* p = (const int4*)CB + j * 2;
        int4 a = p[0], b = p[1];
        union { uint4 v; __half2 h[4]; } u;
        u.h[0] = __halves2half2(__hmul(__int2half_rn(a.x), s), __hmul(__int2half_rn(a.y), s));
        u.h[1] = __halves2half2(__hmul(__int2half_rn(a.z), s), __hmul(__int2half_rn(a.w), s));
        u.h[2] = __halves2half2(__hmul(__int2half_rn(b.x), s), __hmul(__int2half_rn(b.y), s));
        u.h[3] = __halves2half2(__hmul(__int2half_rn(b.z), s), __hmul(__int2half_rn(b.w), s));
        ((uint4*)g_W)[j] = u.v;
    }
}

// ============================================================================
// Kernel 2: mma.sync fp16 GEMM, fp32 accumulators. CTA 128x128x64, 4 warps
// (2x2), warp tile 64x64, 3-stage cp.async pipeline (rotating pointers),
// 2 CTAs/SM, register-double-buffered fragments, interleaved seg2 prefetch,
// single __syncthreads per k-iteration (visibility after CP_WAIT1; anti-dep
// guard = previous iteration's barrier), bias prefetched into registers
// before the mainloop so the epilogue has no dependent global loads.
//
// SW128 swizzle: sw(row, cb) = row*128 + (cb ^ ((row&7)<<4)); per-ks address
// trick: kb ∈ {0,32,64,96} -> addr(ks) = (stage_base + tile_const) ^ kb.
// ============================================================================
__device__ __forceinline__ void ld_frags(uint32_t sa, uint32_t kb,
                                         const uint32_t ta[4], const uint32_t tb[4],
                                         uint32_t RA[4][4], uint32_t RB[4][4]) {
#pragma unroll
    for (int mt = 0; mt < 4; ++mt) {
        uint32_t addr = (sa + ta[mt]) ^ kb;
        asm volatile("ldmatrix.sync.aligned.m8n8.x4.shared.b16 {%0,%1,%2,%3}, [%4];"
            : "=r"(RA[mt][0]), "=r"(RA[mt][1]), "=r"(RA[mt][2]), "=r"(RA[mt][3])
            : "r"(addr));
    }
#pragma unroll
    for (int p = 0; p < 4; ++p) {
        uint32_t addr = (sa + tb[p]) ^ kb;
        asm volatile("ldmatrix.sync.aligned.m8n8.x4.shared.b16 {%0,%1,%2,%3}, [%4];"
            : "=r"(RB[p][0]), "=r"(RB[p][1]), "=r"(RB[p][2]), "=r"(RB[p][3])
            : "r"(addr));
    }
}

#define MMA_ONE(accp, RAf, b0, b1)                                          \
    asm volatile(                                                           \
        "mma.sync.aligned.m16n8k16.row.col.f32.f16.f16.f32 "                \
        "{%0,%1,%2,%3}, {%4,%5,%6,%7}, {%8,%9}, {%0,%1,%2,%3};"             \
        : "+f"((accp)[0]), "+f"((accp)[1]), "+f"((accp)[2]), "+f"((accp)[3])\
        : "r"((RAf)[0]), "r"((RAf)[1]), "r"((RAf)[2]), "r"((RAf)[3]),       \
          "r"(b0), "r"(b1))

__device__ __forceinline__ void mma_all(float acc[4][8][4],
                                        const uint32_t RA[4][4],
                                        const uint32_t RB[4][4]) {
#pragma unroll
    for (int mt = 0; mt < 4; ++mt)
#pragma unroll
        for (int nt = 0; nt < 8; ++nt)
            MMA_ONE(acc[mt][nt], RA[mt],
                    RB[nt >> 1][(nt & 1) * 2], RB[nt >> 1][(nt & 1) * 2 + 1]);
}

// seg2 variant: 32 MMAs with 16 cp.async interleaved (one per 2 MMAs).
__device__ __forceinline__ void mma_all_ld(float acc[4][8][4],
                                           const uint32_t RA[4][4],
                                           const uint32_t RB[4][4],
                                           bool doload,
                                           uint32_t smA, uint32_t smB,
                                           const __half* pA, const __half* pB) {
#pragma unroll
    for (int i = 0; i < 32; ++i) {
        int mt = i >> 3, nt = i & 7;
        MMA_ONE(acc[mt][nt], RA[mt],
                RB[nt >> 1][(nt & 1) * 2], RB[nt >> 1][(nt & 1) * 2 + 1]);
        if (!(i & 1) && doload) {
            int j = i >> 1;                         // 0..15
            if (j < 8) cp_async16(smA + (uint32_t)j * 2048, pA + (size_t)j * 16 * D_IN);
            else       cp_async16(smB + (uint32_t)(j - 8) * 2048,
                                  pB + (size_t)(j - 8) * 16 * D_IN);
        }
    }
}

__global__ __launch_bounds__(128, 2)
void gemm_kernel(const float* __restrict__ biasf,
                 float* __restrict__ out) {
    extern __shared__ char smem[];
    uint32_t sbA = (smem_u32(smem) + 1023u) & ~1023u;   // 1K-aligned stage base
    int tid  = threadIdx.x;
    int lane = tid & 31;
    int wid  = tid >> 5;         // 0..3
    int warp_m = wid >> 1;       // 0..1 (64 rows each)
    int warp_n = wid & 1;        // 0..1 (64 cols each)

    // Grouped rasterization: 8 m-tiles per supergroup, n fastest (B stays in L2)
    const int per = 8 * TILES_N;
    int g  = blockIdx.x / per;
    int r0 = blockIdx.x % per;
    int mi = g * 8 + (r0 & 7);
    int ni = r0 >> 3;
    int m0 = mi * BM;
    int n0 = ni * BN;

    // Per-thread gmem/smem constants for stage loading
    int lr = tid >> 3;           // 0..15
    int lc = tid & 7;            // 16B chunk
    uint32_t cbx = (uint32_t)(lc * 16) ^ (uint32_t)((lr & 7) << 4);
    const __half* pAg = g_X + (size_t)(m0 + lr) * D_IN + lc * 8;
    const __half* pBg = g_W + (size_t)(n0 + lr) * D_IN + lc * 8;
    uint32_t smO = (uint32_t)lr * 128 + cbx;   // smem offset within stage (A part)

    // Tile constants: toff = row*128 + (colbase ^ ((row&7)<<4))
    uint32_t ta[4], tb[4];
    {
        uint32_t acb = (uint32_t)((lane >> 4) * 16);
        uint32_t bcb = (uint32_t)(((lane >> 3) & 1) * 16);
#pragma unroll
        for (int mt = 0; mt < 4; ++mt) {
            int row = warp_m * 64 + mt * 16 + ((lane >> 3) & 1) * 8 + (lane & 7);
            ta[mt] = (uint32_t)row * 128 + (acb ^ (uint32_t)((row & 7) << 4));
        }
#pragma unroll
        for (int p = 0; p < 4; ++p) {
            int row = warp_n * 64 + p * 16 + ((lane >> 4) * 8) + (lane & 7);
            tb[p] = (uint32_t)A_BYTES + (uint32_t)row * 128 +
                    (bcb ^ (uint32_t)((row & 7) << 4));
        }
    }

    // Bias prefetch (epilogue has no dependent global loads afterwards)
    int t2 = (lane & 3) * 2;
    float2 breg[8];
#pragma unroll
    for (int nt = 0; nt < 8; ++nt)
        breg[nt] = *(const float2*)(biasf + n0 + warp_n * 64 + nt * 8 + t2);

    float acc[4][8][4];
#pragma unroll
    for (int i = 0; i < 4; ++i)
#pragma unroll
        for (int j = 0; j < 8; ++j)
#pragma unroll
            for (int q = 0; q < 4; ++q) acc[i][j][q] = 0.0f;

    uint32_t RA[2][4][4], RB[2][4][4];

    // Rotating stage pointers: s0 = stage k, s1 = stage k+1, s2 = stage k+2
    uint32_t s0 = sbA, s1 = sbA + STAGE_BYTES, s2 = sbA + 2 * STAGE_BYTES;

    // Prologue: fill stages 0,1; wait stage 0 (stage 1 stays in flight)
#pragma unroll
    for (int s = 0; s < 2; ++s) {
        uint32_t base = sbA + (uint32_t)s * STAGE_BYTES;
#pragma unroll
        for (int j = 0; j < 8; ++j) {
            cp_async16(base + smO + (uint32_t)j * 2048,
                       pAg + (size_t)j * 16 * D_IN + s * BK);
            cp_async16(base + A_BYTES + smO + (uint32_t)j * 2048,
                       pBg + (size_t)j * 16 * D_IN + s * BK);
        }
        CP_COMMIT();
    }
    CP_WAIT1();
    __syncthreads();
    ld_frags(s0, 0, ta, tb, RA[0], RB[0]);

#pragma unroll 1
    for (int k = 0; k < KITERS; ++k) {
        const bool last = (k == KITERS - 1);

        // seg0: consume buf0, load frags(k, kb=32) into buf1
        ld_frags(s0, 32u, ta, tb, RA[1], RB[1]);
        mma_all(acc, RA[0], RB[0]);

        // seg1: consume buf1, load frags(k, kb=64) into buf0
        ld_frags(s0, 64u, ta, tb, RA[0], RB[0]);
        mma_all(acc, RA[1], RB[1]);

        // seg2: LAST read (kb=96) of stage k into buf1, then consume buf0 with
        // the interleaved stage-(k+2) prefetch (anti-dep guard = PREVIOUS
        // iteration's barrier), then wait + the single barrier.
        ld_frags(s0, 96u, ta, tb, RA[1], RB[1]);
        if (!last) {
            bool doload = (k + 2 < KITERS);
            int k2 = (k + 2) * BK;
            mma_all_ld(acc, RA[0], RB[0], doload,
                       s2 + smO, s2 + A_BYTES + smO, pAg + k2, pBg + k2);
            CP_COMMIT();           // unconditional: uniform group accounting
            CP_WAIT1();            // retires stage-(k+1) group for this warp
            __syncthreads();       // single barrier: visibility of stage k+1
                                   // + anti-dep guard for NEXT iter's cp.asyncs

            // seg3: consume buf1; load frags(k+1, kb=0) from next stage
            ld_frags(s1, 0, ta, tb, RA[0], RB[0]);
            mma_all(acc, RA[1], RB[1]);
        } else {
            // Tail: no prefetch, no downstream consumers — just finish.
            mma_all(acc, RA[0], RB[0]);
            mma_all(acc, RA[1], RB[1]);
        }

        // rotate stage ring
        uint32_t tmp = s0; s0 = s1; s1 = s2; s2 = tmp;
    }

    // Epilogue: fp16(acc_f32) + fp16(bias) (reference rounding chain), upcast
    // to fp32 output. Bias already in registers.
    int gg = lane >> 2;
#pragma unroll
    for (int nt = 0; nt < 8; ++nt) {
        int col = n0 + warp_n * 64 + nt * 8 + t2;
        __half blo = __float2half_rn(breg[nt].x);
        __half bhi = __float2half_rn(breg[nt].y);
#pragma unroll
        for (int mt = 0; mt < 4; ++mt) {
            int row0 = m0 + warp_m * 64 + mt * 16 + gg;
            float2 v0 = make_float2(
                __half2float(__hadd(__float2half_rn(acc[mt][nt][0]), blo)),
                __half2float(__hadd(__float2half_rn(acc[mt][nt][1]), bhi)));
            *(float2*)(out + (size_t)row0 * D_OUT + col) = v0;
            float2 v1 = make_float2(
                __half2float(__hadd(__float2half_rn(acc[mt][nt][2]), blo)),
                __half2float(__hadd(__float2half_rn(acc[mt][nt][3]), bhi)));
            *(float2*)(out + (size_t)(row0 + 8) * D_OUT + col) = v1;
        }
    }
}

// ============================================================================
// Launch
// ============================================================================
extern "C" void kernel_launch(void* const* d_in, const int* in_sizes, int n_in,
                              void* d_out, int out_size) {
    const float* x    = (const float*)d_in[0];
    const int*   CB   = (const int*)d_in[1];
    const float* SCB  = (const float*)d_in[2];
    const float* bias = (const float*)d_in[3];
    float* out = (float*)d_out;

    // 1) Merged prep: x->fp16 and W dequant
    prep_kernel<<<PREP_BLOCKS, 256>>>(x, CB, SCB);

    // 2) Tensor-core GEMM (legacy mma.sync — tcgen05 blocked by the harness's
    //    compute_103 virtual-arch compile; fp16-accum HMMA measured 1x rate),
    //    2 CTAs/SM, 64x64 warp tiles, fragment double-buffering, interleaved
    //    prefetch, single barrier per k-iteration, register-resident bias.
    cudaFuncSetAttribute(gemm_kernel, cudaFuncAttributeMaxDynamicSharedMemorySize,
                         SMEM_BYTES);
    gemm_kernel<<<TILES_M * TILES_N, 128, SMEM_BYTES>>>(bias, out);
}